// round 4
// baseline (speedup 1.0000x reference)
#include <cuda_runtime.h>
#include <cuda_bf16.h>
#include <cstdint>

// ---------------- problem constants ----------------
static constexpr int B_TOTAL = 32768;
static constexpr int DIM     = 256;    // headdim
static constexpr int QTY     = 1625;   // stored patterns
static constexpr int QPADC   = 1664;   // 13 * 128, zero padded
static constexpr int TILE_Q  = 128;
static constexpr int NTILES  = 13;
static constexpr int M_TILE  = 128;
static constexpr int NTHREADS= 256;    // 8 warps
static constexpr float BETA  = 0.0625f; // 1/sqrt(256)

// pre-converted bf16 patterns, zero-padded (scratch via __device__ global)
__device__ __align__(16) __nv_bfloat16 g_patt[QPADC * DIM];

// ---------------- smem layout ----------------
// rows are 256 bf16 = 512B; 16B chunks swizzled: chunk ^= (row & 7)
static constexpr int OFF_F  = 0;        // 64 KB
static constexpr int OFF_P0 = 65536;    // 64 KB
static constexpr int OFF_P1 = 131072;   // 64 KB
static constexpr int OFF_W  = 196608;   // 1 KB (W_out)
static constexpr int SMEM_DYN = 196608 + 1024 + 1024; // + align slack

// ---------------- PTX helpers ----------------
__device__ __forceinline__ uint32_t smem_u32(const void* p) {
    uint32_t a;
    asm("{ .reg .u64 t; cvta.to.shared.u64 t, %1; cvt.u32.u64 %0, t; }" : "=r"(a) : "l"(p));
    return a;
}
#define STS128(a, r0, r1, r2, r3) \
    asm volatile("st.shared.v4.b32 [%0], {%1,%2,%3,%4};" :: "r"(a), "r"(r0), "r"(r1), "r"(r2), "r"(r3) : "memory")
#define CVTBF2(res, lo, hi) \
    asm("cvt.rn.bf16x2.f32 %0, %1, %2;" : "=r"(res) : "f"(hi), "f"(lo))
#define CP_ASYNC16(dst, src) \
    asm volatile("cp.async.cg.shared.global [%0], [%1], 16;" :: "r"(dst), "l"(src) : "memory")
#define CP_COMMIT() asm volatile("cp.async.commit_group;" ::: "memory")
#define CP_WAIT1()  asm volatile("cp.async.wait_group 1;" ::: "memory")
#define CP_WAIT0()  asm volatile("cp.async.wait_group 0;" ::: "memory")

__device__ __forceinline__ void ldsm_x4(uint32_t& r0, uint32_t& r1, uint32_t& r2, uint32_t& r3, uint32_t a) {
    asm volatile("ldmatrix.sync.aligned.m8n8.x4.shared.b16 {%0,%1,%2,%3}, [%4];"
        : "=r"(r0), "=r"(r1), "=r"(r2), "=r"(r3) : "r"(a));
}
__device__ __forceinline__ void ldsm_x4_t(uint32_t& r0, uint32_t& r1, uint32_t& r2, uint32_t& r3, uint32_t a) {
    asm volatile("ldmatrix.sync.aligned.m8n8.x4.trans.shared.b16 {%0,%1,%2,%3}, [%4];"
        : "=r"(r0), "=r"(r1), "=r"(r2), "=r"(r3) : "r"(a));
}
__device__ __forceinline__ void mma16816(float* c, uint32_t a0, uint32_t a1, uint32_t a2, uint32_t a3,
                                         uint32_t b0, uint32_t b1) {
    asm volatile("mma.sync.aligned.m16n8k16.row.col.f32.bf16.bf16.f32 "
        "{%0,%1,%2,%3}, {%4,%5,%6,%7}, {%8,%9}, {%0,%1,%2,%3};"
        : "+f"(c[0]), "+f"(c[1]), "+f"(c[2]), "+f"(c[3])
        : "r"(a0), "r"(a1), "r"(a2), "r"(a3), "r"(b0), "r"(b1));
}

// swizzled byte offset of 16B chunk (row, chunkcol in 0..31)
__device__ __forceinline__ uint32_t swz(int row, int cc) {
    return (uint32_t)row * 512u + (uint32_t)(((cc ^ (row & 7)) & 31) << 4);
}

// ---------------- prologue: fp32 patterns -> padded bf16 ----------------
__global__ void convert_patterns_kernel(const float* __restrict__ patterns) {
    int i = blockIdx.x * blockDim.x + threadIdx.x;
    if (i >= QPADC * DIM) return;
    int q = i >> 8;
    int d = i & (DIM - 1);
    g_patt[i] = (q < QTY) ? __float2bfloat16(patterns[q * DIM + d]) : __nv_bfloat16(0.f);
}

// ---------------- P tile prefetch (cp.async) ----------------
__device__ __forceinline__ void prefetch_P(uint32_t dstbase, int q0, int tid) {
    #pragma unroll
    for (int k = 0; k < 16; ++k) {
        int i   = tid + k * NTHREADS;      // 0 .. 4095
        int row = i >> 5;
        int cc  = i & 31;
        CP_ASYNC16(dstbase + swz(row, cc),
                   (const char*)(g_patt + (size_t)(q0 + row) * DIM + cc * 8));
    }
    CP_COMMIT();
}

// ---------------- main fused kernel ----------------
__global__ void __launch_bounds__(NTHREADS, 1)
hopfield_main(const float* __restrict__ features,
              const float* __restrict__ W_out,
              const float* __restrict__ b_out,
              float* __restrict__ out)
{
    extern __shared__ char smem_raw[];
    const uint32_t raw  = smem_u32(smem_raw);
    const uint32_t base = (raw + 1023u) & ~1023u;
    char* smem = smem_raw + (base - raw);

    const int tid  = threadIdx.x;
    const int wid  = tid >> 5;
    const int lane = tid & 31;
    const int b0   = blockIdx.x * M_TILE;
    const int m0   = wid * 16;

    float* W_sm = (float*)(smem + OFF_W);
    if (tid < DIM) W_sm[tid] = W_out[tid];

    // kick off P tile 0 prefetch before doing the F conversion
    prefetch_P(base + OFF_P0, 0, tid);

    // features tile -> bf16 swizzled SMEM
    #pragma unroll
    for (int k = 0; k < 16; ++k) {
        int i   = tid + k * NTHREADS;
        int row = i >> 5;
        int cc  = i & 31;
        const float4* src = (const float4*)(features + (size_t)(b0 + row) * DIM + cc * 8);
        float4 v0 = src[0];
        float4 v1 = src[1];
        uint32_t p0, p1, p2, p3;
        CVTBF2(p0, v0.x, v0.y); CVTBF2(p1, v0.z, v0.w);
        CVTBF2(p2, v1.x, v1.y); CVTBF2(p3, v1.z, v1.w);
        STS128(base + OFF_F + swz(row, cc), p0, p1, p2, p3);
    }

    float oacc[32][4];
    #pragma unroll
    for (int i = 0; i < 32; ++i) {
        oacc[i][0] = 0.f; oacc[i][1] = 0.f; oacc[i][2] = 0.f; oacc[i][3] = 0.f;
    }
    float lacc0 = 0.f, lacc1 = 0.f;

    // precomputed ldmatrix lane addressing pieces
    const int arow_off  = lane & 15;          // row within 16-row group
    const int achunk_off = lane >> 4;         // 0/1 -> k chunk select
    const int bsel      = (lane >> 3) & 1;    // GEMM1 B: k-chunk select

    for (int t = 0; t < NTILES; ++t) {
        const int q0 = t * TILE_Q;
        const uint32_t pcur = base + ((t & 1) ? OFF_P1 : OFF_P0);

        if (t + 1 < NTILES) {
            prefetch_P(base + ((t & 1) ? OFF_P0 : OFF_P1), q0 + TILE_Q, tid);
            CP_WAIT1();
        } else {
            CP_WAIT0();
        }
        __syncthreads();

        // ---- GEMM1: S[16 x 128] = F[16 x 256] @ P^T ----
        float sacc[16][4];
        #pragma unroll
        for (int i = 0; i < 16; ++i) {
            sacc[i][0] = 0.f; sacc[i][1] = 0.f; sacc[i][2] = 0.f; sacc[i][3] = 0.f;
        }
        #pragma unroll
        for (int ks = 0; ks < 16; ++ks) {
            const int kc = ks * 2;            // 16 elems = 2 chunks
            uint32_t a0, a1, a2, a3;
            ldsm_x4(a0, a1, a2, a3, base + OFF_F + swz(m0 + arow_off, kc + achunk_off));
            #pragma unroll
            for (int nt = 0; nt < 8; ++nt) {
                const int qrow = nt * 16 + (lane & 7) + ((lane >> 4) << 3);
                uint32_t b0r, b1r, b2r, b3r;
                ldsm_x4(b0r, b1r, b2r, b3r, pcur + swz(qrow, kc + bsel));
                mma16816(sacc[2 * nt],     a0, a1, a2, a3, b0r, b1r);
                mma16816(sacc[2 * nt + 1], a0, a1, a2, a3, b2r, b3r);
            }
        }

        // ---- softmax (no running max needed: |s*beta| < ~0.5) + pack A frags ----
        uint32_t ap[8][4];
        #pragma unroll
        for (int nt = 0; nt < 16; ++nt) {
            const int qg = q0 + nt * 8 + (lane & 3) * 2;
            float e0 = __expf(sacc[nt][0] * BETA);
            float e1 = __expf(sacc[nt][1] * BETA);
            float e2 = __expf(sacc[nt][2] * BETA);
            float e3 = __expf(sacc[nt][3] * BETA);
            if (qg     >= QTY) { e0 = 0.f; e2 = 0.f; }
            if (qg + 1 >= QTY) { e1 = 0.f; e3 = 0.f; }
            lacc0 += e0 + e1;
            lacc1 += e2 + e3;
            CVTBF2(ap[nt >> 1][(nt & 1) * 2],     e0, e1);   // rows r
            CVTBF2(ap[nt >> 1][(nt & 1) * 2 + 1], e2, e3);   // rows r+8
        }

        // ---- GEMM2: O[16 x 256] += attn[16 x 128] @ P ----
        #pragma unroll
        for (int kt = 0; kt < 8; ++kt) {
            const int qk = kt * 16;
            const int prow = qk + arow_off;   // lanes0-7:q0-7, 8-15:q8-15, 16-23:q0-7, 24-31:q8-15
            #pragma unroll
            for (int dt = 0; dt < 16; ++dt) {
                const int cch = dt * 2 + achunk_off;
                uint32_t b0r, b1r, b2r, b3r;
                ldsm_x4_t(b0r, b1r, b2r, b3r, pcur + swz(prow, cch));
                mma16816(oacc[2 * dt],     ap[kt][0], ap[kt][1], ap[kt][2], ap[kt][3], b0r, b1r);
                mma16816(oacc[2 * dt + 1], ap[kt][0], ap[kt][1], ap[kt][2], ap[kt][3], b2r, b3r);
            }
        }
        __syncthreads();   // all warps done reading pcur before next prefetch overwrites it
    }

    // ---- epilogue: l reduce, dot(O, W), sigmoid ----
    lacc0 += __shfl_xor_sync(0xffffffffu, lacc0, 1);
    lacc0 += __shfl_xor_sync(0xffffffffu, lacc0, 2);
    lacc1 += __shfl_xor_sync(0xffffffffu, lacc1, 1);
    lacc1 += __shfl_xor_sync(0xffffffffu, lacc1, 2);

    float p0 = 0.f, p1 = 0.f;
    #pragma unroll
    for (int dt = 0; dt < 32; ++dt) {
        const int d = dt * 8 + (lane & 3) * 2;
        const float w0 = W_sm[d];
        const float w1 = W_sm[d + 1];
        p0 += oacc[dt][0] * w0 + oacc[dt][1] * w1;
        p1 += oacc[dt][2] * w0 + oacc[dt][3] * w1;
    }
    p0 += __shfl_xor_sync(0xffffffffu, p0, 1);
    p0 += __shfl_xor_sync(0xffffffffu, p0, 2);
    p1 += __shfl_xor_sync(0xffffffffu, p1, 1);
    p1 += __shfl_xor_sync(0xffffffffu, p1, 2);

    if ((lane & 3) == 0) {
        const float bb = b_out[0];
        const int r = b0 + m0 + (lane >> 2);
        const float lg0 = p0 / lacc0 + bb;
        const float lg1 = p1 / lacc1 + bb;
        out[r]     = __fdividef(1.f, 1.f + __expf(-lg0));
        out[r + 8] = __fdividef(1.f, 1.f + __expf(-lg1));
    }
}

// ---------------- launch ----------------
extern "C" void kernel_launch(void* const* d_in, const int* in_sizes, int n_in,
                              void* d_out, int out_size) {
    (void)in_sizes; (void)n_in; (void)out_size;
    const float* features = (const float*)d_in[0];
    const float* patterns = (const float*)d_in[1];
    const float* W_out    = (const float*)d_in[2];
    const float* b_out    = (const float*)d_in[3];
    float* out = (float*)d_out;

    cudaFuncSetAttribute(hopfield_main,
                         cudaFuncAttributeMaxDynamicSharedMemorySize, SMEM_DYN);

    convert_patterns_kernel<<<(QPADC * DIM + 255) / 256, 256>>>(patterns);
    hopfield_main<<<B_TOTAL / M_TILE, NTHREADS, SMEM_DYN>>>(features, W_out, b_out, out);
}

// round 5
// speedup vs baseline: 1.7964x; 1.7964x over previous
#include <cuda_runtime.h>
#include <cuda_bf16.h>
#include <cstdint>

// ---------------- problem constants ----------------
static constexpr int B_TOTAL = 32768;
static constexpr int DIM     = 256;     // headdim
static constexpr int QTY     = 1625;    // stored patterns
static constexpr int QPADC   = 1664;    // 13 * 128, zero padded
static constexpr int TILE_Q  = 128;
static constexpr int NTILES  = 13;
static constexpr int M_TILE  = 128;
static constexpr int NTHREADS= 256;     // 8 warps
static constexpr float BETA  = 0.0625f; // 1/sqrt(256)

// scratch via __device__ globals (no allocs)
__device__ __align__(16) __nv_bfloat16 g_patt[QPADC * DIM];  // bf16 patterns, zero-padded
__device__ __align__(16) float          g_pw[QPADC];          // pw[q] = patterns[q] . W  (0 for pads)

// ---------------- smem layout ----------------
// rows are 256 bf16 = 512B; 16B chunks swizzled: chunk ^= (row & 7)
static constexpr int OFF_P0 = 0;        // 64 KB  P tile buffer 0
static constexpr int OFF_P1 = 65536;    // 64 KB  P tile buffer 1
static constexpr int OFF_F  = 131072;   // 64 KB  features tile (read once into regs)
static constexpr int OFF_PW = 196608;   // 6656 B pw cache
static constexpr int SMEM_DYN = 196608 + 6656 + 1024;  // + align slack

// ---------------- PTX helpers ----------------
__device__ __forceinline__ uint32_t smem_u32(const void* p) {
    uint32_t a;
    asm("{ .reg .u64 t; cvta.to.shared.u64 t, %1; cvt.u32.u64 %0, t; }" : "=r"(a) : "l"(p));
    return a;
}
#define STS128(a, r0, r1, r2, r3) \
    asm volatile("st.shared.v4.b32 [%0], {%1,%2,%3,%4};" :: "r"(a), "r"(r0), "r"(r1), "r"(r2), "r"(r3) : "memory")
#define CVTBF2(res, lo, hi) \
    asm("cvt.rn.bf16x2.f32 %0, %1, %2;" : "=r"(res) : "f"(hi), "f"(lo))
#define CP_ASYNC16(dst, src) \
    asm volatile("cp.async.cg.shared.global [%0], [%1], 16;" :: "r"(dst), "l"(src) : "memory")
#define CP_COMMIT() asm volatile("cp.async.commit_group;" ::: "memory")
#define CP_WAIT1()  asm volatile("cp.async.wait_group 1;" ::: "memory")
#define CP_WAIT0()  asm volatile("cp.async.wait_group 0;" ::: "memory")

__device__ __forceinline__ void ldsm_x4(uint32_t& r0, uint32_t& r1, uint32_t& r2, uint32_t& r3, uint32_t a) {
    asm volatile("ldmatrix.sync.aligned.m8n8.x4.shared.b16 {%0,%1,%2,%3}, [%4];"
        : "=r"(r0), "=r"(r1), "=r"(r2), "=r"(r3) : "r"(a));
}
__device__ __forceinline__ void mma16816(float* c, uint32_t a0, uint32_t a1, uint32_t a2, uint32_t a3,
                                         uint32_t b0, uint32_t b1) {
    asm volatile("mma.sync.aligned.m16n8k16.row.col.f32.bf16.bf16.f32 "
        "{%0,%1,%2,%3}, {%4,%5,%6,%7}, {%8,%9}, {%0,%1,%2,%3};"
        : "+f"(c[0]), "+f"(c[1]), "+f"(c[2]), "+f"(c[3])
        : "r"(a0), "r"(a1), "r"(a2), "r"(a3), "r"(b0), "r"(b1));
}

// swizzled byte offset of 16B chunk (row, chunkcol in 0..31)
__device__ __forceinline__ uint32_t swz(int row, int cc) {
    return (uint32_t)row * 512u + (uint32_t)(((cc ^ (row & 7)) & 31) << 4);
}

// ---------------- prologue kernels ----------------
__global__ void convert_patterns_kernel(const float* __restrict__ patterns) {
    int i = blockIdx.x * blockDim.x + threadIdx.x;
    if (i >= QPADC * DIM) return;
    int q = i >> 8;
    int d = i & (DIM - 1);
    g_patt[i] = (q < QTY) ? __float2bfloat16(patterns[q * DIM + d]) : __nv_bfloat16(0.f);
}

// pw[q] = patterns[q] . W   (fp32, warp per q)
__global__ void pw_kernel(const float* __restrict__ patterns, const float* __restrict__ W_out) {
    int q    = blockIdx.x * 8 + (threadIdx.x >> 5);
    int lane = threadIdx.x & 31;
    if (q >= QPADC) return;
    float s = 0.f;
    if (q < QTY) {
        const float* row = patterns + (size_t)q * DIM;
        #pragma unroll
        for (int d = lane; d < DIM; d += 32) s += row[d] * W_out[d];
        #pragma unroll
        for (int o = 16; o > 0; o >>= 1) s += __shfl_xor_sync(0xffffffffu, s, o);
    }
    if (lane == 0) g_pw[q] = s;
}

// ---------------- P tile prefetch (cp.async) ----------------
__device__ __forceinline__ void prefetch_P(uint32_t dstbase, int q0, int tid) {
    #pragma unroll
    for (int k = 0; k < 16; ++k) {
        int i   = tid + k * NTHREADS;      // 0 .. 4095
        int row = i >> 5;
        int cc  = i & 31;
        CP_ASYNC16(dstbase + swz(row, cc),
                   (const char*)(g_patt + (size_t)(q0 + row) * DIM + cc * 8));
    }
    CP_COMMIT();
}

// ---------------- main fused kernel ----------------
__global__ void __launch_bounds__(NTHREADS, 1)
hopfield_main(const float* __restrict__ features,
              const float* __restrict__ b_out,
              float* __restrict__ out)
{
    extern __shared__ char smem_raw[];
    const uint32_t raw  = smem_u32(smem_raw);
    const uint32_t base = (raw + 1023u) & ~1023u;
    char* smem = smem_raw + (base - raw);

    const int tid  = threadIdx.x;
    const int wid  = tid >> 5;
    const int lane = tid & 31;
    const int b0   = blockIdx.x * M_TILE;
    const int m0   = wid * 16;

    // kick off P tile 0 prefetch first
    prefetch_P(base + OFF_P0, 0, tid);

    // pw table -> smem
    float* pw_sm = (float*)(smem + OFF_PW);
    #pragma unroll
    for (int i = tid; i < QPADC; i += NTHREADS) pw_sm[i] = g_pw[i];

    // features tile -> bf16 swizzled SMEM (read exactly once into regs below)
    #pragma unroll
    for (int k = 0; k < 16; ++k) {
        int i   = tid + k * NTHREADS;
        int row = i >> 5;
        int cc  = i & 31;
        const float4* src = (const float4*)(features + (size_t)(b0 + row) * DIM + cc * 8);
        float4 v0 = src[0];
        float4 v1 = src[1];
        uint32_t p0, p1, p2, p3;
        CVTBF2(p0, v0.x, v0.y); CVTBF2(p1, v0.z, v0.w);
        CVTBF2(p2, v1.x, v1.y); CVTBF2(p3, v1.z, v1.w);
        STS128(base + OFF_F + swz(row, cc), p0, p1, p2, p3);
    }
    __syncthreads();

    // ldmatrix lane addressing pieces
    const int arow_off   = lane & 15;
    const int achunk_off = lane >> 4;
    const int bsel       = (lane >> 3) & 1;

    // hoist the 16 F A-fragments (this warp's 16 rows x full K=256) into registers
    uint32_t fa[16][4];
    #pragma unroll
    for (int ks = 0; ks < 16; ++ks)
        ldsm_x4(fa[ks][0], fa[ks][1], fa[ks][2], fa[ks][3],
                base + OFF_F + swz(m0 + arow_off, 2 * ks + achunk_off));

    float lacc0 = 0.f, lacc1 = 0.f, pacc0 = 0.f, pacc1 = 0.f;
    const int colq = (lane & 3) * 2;

    for (int t = 0; t < NTILES; ++t) {
        const int q0 = t * TILE_Q;
        const uint32_t pcur = base + ((t & 1) ? OFF_P1 : OFF_P0);

        if (t + 1 < NTILES) {
            prefetch_P(base + ((t & 1) ? OFF_P0 : OFF_P1), q0 + TILE_Q, tid);
            CP_WAIT1();
        } else {
            CP_WAIT0();
        }
        __syncthreads();

        // ---- GEMM1: S[16 x 128] = F[16 x 256] @ P^T ----
        float sacc[16][4];
        #pragma unroll
        for (int i = 0; i < 16; ++i) {
            sacc[i][0] = 0.f; sacc[i][1] = 0.f; sacc[i][2] = 0.f; sacc[i][3] = 0.f;
        }
        #pragma unroll
        for (int ks = 0; ks < 16; ++ks) {
            const int kc = ks * 2;
            #pragma unroll
            for (int nt = 0; nt < 8; ++nt) {
                const int qrow = nt * 16 + (lane & 7) + ((lane >> 4) << 3);
                uint32_t b0r, b1r, b2r, b3r;
                ldsm_x4(b0r, b1r, b2r, b3r, pcur + swz(qrow, kc + bsel));
                mma16816(sacc[2 * nt],     fa[ks][0], fa[ks][1], fa[ks][2], fa[ks][3], b0r, b1r);
                mma16816(sacc[2 * nt + 1], fa[ks][0], fa[ks][1], fa[ks][2], fa[ks][3], b2r, b3r);
            }
        }

        // ---- softmax terms + fused pw dot (GEMM2 eliminated: OUT==1) ----
        if (t < NTILES - 1) {
            #pragma unroll
            for (int nt = 0; nt < 16; ++nt) {
                const float2 pw = *(const float2*)(pw_sm + q0 + nt * 8 + colq);
                const float e0 = __expf(sacc[nt][0] * BETA);
                const float e1 = __expf(sacc[nt][1] * BETA);
                const float e2 = __expf(sacc[nt][2] * BETA);
                const float e3 = __expf(sacc[nt][3] * BETA);
                lacc0 += e0 + e1;            lacc1 += e2 + e3;
                pacc0 += e0 * pw.x + e1 * pw.y;
                pacc1 += e2 * pw.x + e3 * pw.y;
            }
        } else {
            #pragma unroll
            for (int nt = 0; nt < 16; ++nt) {
                const int qg = q0 + nt * 8 + colq;
                const float2 pw = *(const float2*)(pw_sm + qg);
                float e0 = __expf(sacc[nt][0] * BETA);
                float e1 = __expf(sacc[nt][1] * BETA);
                float e2 = __expf(sacc[nt][2] * BETA);
                float e3 = __expf(sacc[nt][3] * BETA);
                if (qg     >= QTY) { e0 = 0.f; e2 = 0.f; }
                if (qg + 1 >= QTY) { e1 = 0.f; e3 = 0.f; }
                lacc0 += e0 + e1;            lacc1 += e2 + e3;
                pacc0 += e0 * pw.x + e1 * pw.y;
                pacc1 += e2 * pw.x + e3 * pw.y;
            }
        }
        __syncthreads();   // all warps done reading pcur before next prefetch overwrites it
    }

    // ---- epilogue: reduce over the 4 column-lanes, sigmoid ----
    #pragma unroll
    for (int o = 1; o <= 2; o <<= 1) {
        lacc0 += __shfl_xor_sync(0xffffffffu, lacc0, o);
        lacc1 += __shfl_xor_sync(0xffffffffu, lacc1, o);
        pacc0 += __shfl_xor_sync(0xffffffffu, pacc0, o);
        pacc1 += __shfl_xor_sync(0xffffffffu, pacc1, o);
    }
    if ((lane & 3) == 0) {
        const float bb = b_out[0];
        const int r = b0 + m0 + (lane >> 2);
        const float lg0 = pacc0 / lacc0 + bb;
        const float lg1 = pacc1 / lacc1 + bb;
        out[r]     = __fdividef(1.f, 1.f + __expf(-lg0));
        out[r + 8] = __fdividef(1.f, 1.f + __expf(-lg1));
    }
}

// ---------------- launch ----------------
extern "C" void kernel_launch(void* const* d_in, const int* in_sizes, int n_in,
                              void* d_out, int out_size) {
    (void)in_sizes; (void)n_in; (void)out_size;
    const float* features = (const float*)d_in[0];
    const float* patterns = (const float*)d_in[1];
    const float* W_out    = (const float*)d_in[2];
    const float* b_out    = (const float*)d_in[3];
    float* out = (float*)d_out;

    cudaFuncSetAttribute(hopfield_main,
                         cudaFuncAttributeMaxDynamicSharedMemorySize, SMEM_DYN);

    convert_patterns_kernel<<<(QPADC * DIM + 255) / 256, 256>>>(patterns);
    pw_kernel<<<QPADC / 8, 256>>>(patterns, W_out);
    hopfield_main<<<B_TOTAL / M_TILE, NTHREADS, SMEM_DYN>>>(features, b_out, out);
}